// round 7
// baseline (speedup 1.0000x reference)
#include <cuda_runtime.h>
#include <cuda_bf16.h>
#include <cstdint>

// DistMult: C[i,j] = sum_k (A[i,k]*w_r[k]) * B[j,k] + bias
// R7: split-bf16 mma.sync GEMM, 512 threads/CTA (4 warps/SMSP), warp tile
// 32x64, single barrier per k-tile, within-tile ldmatrix/MMA pipelining.
// K'=1536: A'=[Ahi|Ahi|Alo], B'=[Bhi|Blo|Bhi]  (fp32 accum, rel err ~5e-6)

#define DM_D   512
#define DM_KP  1536
#define DM_N1  8192
#define DM_N2  8192
#define DM_BM  128
#define DM_BN  256
#define DM_BK  32
#define DM_KT  (DM_KP / DM_BK)   // 48
#define STAGES 3

__device__ __nv_bfloat16 g_A2[(size_t)DM_N1 * DM_KP];
__device__ __nv_bfloat16 g_B2[(size_t)DM_N2 * DM_KP];

// ---------------- PTX helpers ----------------
__device__ __forceinline__ uint32_t smem_u32(const void* p) {
    uint32_t a;
    asm("{ .reg .u64 t; cvta.to.shared.u64 t, %1; cvt.u32.u64 %0, t; }"
        : "=r"(a) : "l"(p));
    return a;
}

#define CP_ASYNC16(saddr, gptr) \
    asm volatile("cp.async.cg.shared.global [%0], [%1], 16;" :: "r"(saddr), "l"(gptr))
#define CP_COMMIT() asm volatile("cp.async.commit_group;" ::: "memory")
#define CP_WAIT(n)  asm volatile("cp.async.wait_group %0;" :: "n"(n) : "memory")

__device__ __forceinline__ void ldmx4(uint32_t* r, uint32_t addr) {
    asm volatile("ldmatrix.sync.aligned.m8n8.x4.shared.b16 {%0,%1,%2,%3}, [%4];"
                 : "=r"(r[0]), "=r"(r[1]), "=r"(r[2]), "=r"(r[3]) : "r"(addr));
}

__device__ __forceinline__ void mma16816(float* d, const uint32_t* a,
                                         uint32_t b0, uint32_t b1) {
    asm volatile(
        "mma.sync.aligned.m16n8k16.row.col.f32.bf16.bf16.f32 "
        "{%0,%1,%2,%3}, {%4,%5,%6,%7}, {%8,%9}, {%0,%1,%2,%3};"
        : "+f"(d[0]), "+f"(d[1]), "+f"(d[2]), "+f"(d[3])
        : "r"(a[0]), "r"(a[1]), "r"(a[2]), "r"(a[3]), "r"(b0), "r"(b1));
}

// ---------------- Pass 1: split conversion ----------------
__global__ __launch_bounds__(256)
void dm_convert_kernel(const float* __restrict__ A, const float* __restrict__ B,
                       const float* __restrict__ W, const int* __restrict__ tip) {
    const int idx = blockIdx.x * 256 + threadIdx.x;
    const int r  = idx >> 7;
    const int c4 = (idx & 127) * 4;
    const int ti = tip[0];

    const float4 w = *(const float4*)(W + (size_t)ti * DM_D + c4);
    const float4 a = *(const float4*)(A + (size_t)r * DM_D + c4);
    const float4 b = *(const float4*)(B + (size_t)r * DM_D + c4);

    float as[4] = {a.x * w.x, a.y * w.y, a.z * w.z, a.w * w.w};
    float bs[4] = {b.x, b.y, b.z, b.w};

    __nv_bfloat16 ah[4], al[4], bh[4], bl[4];
    #pragma unroll
    for (int i = 0; i < 4; i++) {
        ah[i] = __float2bfloat16_rn(as[i]);
        al[i] = __float2bfloat16_rn(as[i] - __bfloat162float(ah[i]));
        bh[i] = __float2bfloat16_rn(bs[i]);
        bl[i] = __float2bfloat16_rn(bs[i] - __bfloat162float(bh[i]));
    }

    __nv_bfloat16* arow = g_A2 + (size_t)r * DM_KP;
    __nv_bfloat16* brow = g_B2 + (size_t)r * DM_KP;
    *(uint2*)(arow + c4)        = *(uint2*)ah;
    *(uint2*)(arow + 512 + c4)  = *(uint2*)ah;
    *(uint2*)(arow + 1024 + c4) = *(uint2*)al;
    *(uint2*)(brow + c4)        = *(uint2*)bh;
    *(uint2*)(brow + 512 + c4)  = *(uint2*)bl;
    *(uint2*)(brow + 1024 + c4) = *(uint2*)bh;
}

// ---------------- Pass 2: GEMM ----------------
// smem: sA[STAGES][128][64B], sB[STAGES][256][64B]
// swizzle: chunk c at row r -> chunk (c ^ ((r>>1)&3))
#define STG_A 8192
#define STG_B 16384
#define SMEM_TOTAL (STAGES * (STG_A + STG_B))   // 73728

__global__ __launch_bounds__(512, 1)
void dm_gemm_kernel(const float* __restrict__ bias, float* __restrict__ C) {
    extern __shared__ char smem[];
    const uint32_t sAb = smem_u32(smem);
    const uint32_t sBb = sAb + STAGES * STG_A;

    const int tid  = threadIdx.x;
    const int wid  = tid >> 5;
    const int lane = tid & 31;
    const int warp_m = wid & 3;       // 4 warps over M (32 rows each)
    const int warp_n = wid >> 2;      // 4 warps over N (64 cols each)

    const int row0 = blockIdx.y * DM_BM;
    const int col0 = blockIdx.x * DM_BN;

    // ldmatrix address precompute
    const int tile  = lane >> 3;
    const int lrow8 = lane & 7;
    const int a_trow = (tile & 1) * 8;
    const int a_tcol = tile >> 1;          // 0/1 : k-halves
    uint32_t aByte[2]; int aMask[2];
    #pragma unroll
    for (int mi = 0; mi < 2; mi++) {
        int r = warp_m * 32 + mi * 16 + a_trow + lrow8;
        aByte[mi] = r * 64;
        aMask[mi] = (r >> 1) & 3;
    }
    const int b_trow = (tile >> 1) * 8;
    const int b_tcol = tile & 1;
    uint32_t bByte[4]; int bMask[4];
    #pragma unroll
    for (int ni = 0; ni < 4; ni++) {
        int r = warp_n * 64 + ni * 16 + b_trow + lrow8;
        bByte[ni] = r * 64;
        bMask[ni] = (r >> 1) & 3;
    }

    float acc[2][8][4];
    #pragma unroll
    for (int mi = 0; mi < 2; mi++)
        #pragma unroll
        for (int nf = 0; nf < 8; nf++)
            #pragma unroll
            for (int q = 0; q < 4; q++) acc[mi][nf][q] = 0.0f;

    // tile loader: A 512 chunks (1/thread), B 1024 chunks (2/thread)
    auto load_tile = [&](int kt, int s) {
        const int kb = kt * DM_BK;
        {
            int r = tid >> 2, c = tid & 3;
            const __nv_bfloat16* g = g_A2 + (size_t)(row0 + r) * DM_KP + kb + c * 8;
            uint32_t sa = sAb + s * STG_A + r * 64 + ((c ^ ((r >> 1) & 3)) << 4);
            CP_ASYNC16(sa, g);
        }
        #pragma unroll
        for (int i = 0; i < 2; i++) {
            int idx = tid + i * 512;
            int r = idx >> 2, c = idx & 3;
            const __nv_bfloat16* g = g_B2 + (size_t)(col0 + r) * DM_KP + kb + c * 8;
            uint32_t sb = sBb + s * STG_B + r * 64 + ((c ^ ((r >> 1) & 3)) << 4);
            CP_ASYNC16(sb, g);
        }
    };

    // prologue
    #pragma unroll
    for (int s = 0; s < STAGES - 1; s++) {
        load_tile(s, s);
        CP_COMMIT();
    }

    // mainloop: ONE barrier per k-tile; within-tile frag pipelining
    for (int kt = 0; kt < DM_KT; kt++) {
        CP_WAIT(STAGES - 2);
        __syncthreads();

        if (kt + STAGES - 1 < DM_KT) {
            load_tile(kt + STAGES - 1, (kt + STAGES - 1) % STAGES);
            CP_COMMIT();
        }

        const int s = kt % STAGES;
        const uint32_t sa0 = sAb + s * STG_A;
        const uint32_t sb0 = sBb + s * STG_B;

        uint32_t afr[2][2][4], bfr[2][4][4];
        // prefetch ks=0 fragments
        #pragma unroll
        for (int mi = 0; mi < 2; mi++)
            ldmx4(afr[0][mi], sa0 + aByte[mi] + ((a_tcol ^ aMask[mi]) << 4));
        #pragma unroll
        for (int ni = 0; ni < 4; ni++)
            ldmx4(bfr[0][ni], sb0 + bByte[ni] + ((b_tcol ^ bMask[ni]) << 4));

        #pragma unroll
        for (int ks = 0; ks < 2; ks++) {
            if (ks == 0) {
                // prefetch ks=1 fragments (overlaps with MMA below)
                #pragma unroll
                for (int mi = 0; mi < 2; mi++)
                    ldmx4(afr[1][mi], sa0 + aByte[mi] +
                                      (((2 + a_tcol) ^ aMask[mi]) << 4));
                #pragma unroll
                for (int ni = 0; ni < 4; ni++)
                    ldmx4(bfr[1][ni], sb0 + bByte[ni] +
                                      (((2 + b_tcol) ^ bMask[ni]) << 4));
            }
            #pragma unroll
            for (int mi = 0; mi < 2; mi++)
                #pragma unroll
                for (int ni = 0; ni < 4; ni++) {
                    mma16816(acc[mi][ni * 2 + 0], afr[ks][mi],
                             bfr[ks][ni][0], bfr[ks][ni][1]);
                    mma16816(acc[mi][ni * 2 + 1], afr[ks][mi],
                             bfr[ks][ni][2], bfr[ks][ni][3]);
                }
        }
        // no bottom barrier: next iteration's top barrier protects stage reuse
    }

    // epilogue
    const float bv = bias[0];
    const int er = lane >> 2;
    const int ec = (lane & 3) * 2;
    #pragma unroll
    for (int mi = 0; mi < 2; mi++) {
        const int rgl = row0 + warp_m * 32 + mi * 16 + er;
        float* c0 = C + (size_t)rgl * DM_N2 + col0 + warp_n * 64 + ec;
        float* c1 = C + (size_t)(rgl + 8) * DM_N2 + col0 + warp_n * 64 + ec;
        #pragma unroll
        for (int nf = 0; nf < 8; nf++) {
            float2 v0 = {acc[mi][nf][0] + bv, acc[mi][nf][1] + bv};
            float2 v1 = {acc[mi][nf][2] + bv, acc[mi][nf][3] + bv};
            *(float2*)(c0 + nf * 8) = v0;
            *(float2*)(c1 + nf * 8) = v1;
        }
    }
}

// ---------------- launch ----------------
extern "C" void kernel_launch(void* const* d_in, const int* in_sizes, int n_in,
                              void* d_out, int out_size) {
    const float* input1     = (const float*)d_in[0];
    const float* input2     = (const float*)d_in[1];
    const float* weight     = (const float*)d_in[2];
    const float* bias       = (const float*)d_in[3];
    const int*   type_index = (const int*)  d_in[4];
    float*       out        = (float*)d_out;

    cudaFuncSetAttribute(dm_gemm_kernel,
                         cudaFuncAttributeMaxDynamicSharedMemorySize, SMEM_TOTAL);

    dm_convert_kernel<<<DM_N1 * DM_D / 4 / 256, 256>>>(
        input1, input2, weight, type_index);

    dim3 grid(DM_N2 / DM_BN, DM_N1 / DM_BM);
    dm_gemm_kernel<<<grid, 512, SMEM_TOTAL>>>(bias, out);
}

// round 8
// speedup vs baseline: 1.2597x; 1.2597x over previous
#include <cuda_runtime.h>
#include <cuda_bf16.h>
#include <cstdint>

// DistMult: C[i,j] = sum_k (A[i,k]*w_r[k]) * B[j,k] + bias
// R8: R6 layout (256 thr, 8 warps, 64x64 warp tile) + BK=64 (halves barriers),
// full SW128 swizzle, rolling ks+1 fragment prefetch inside each k-tile.
// K'=1536: A'=[Ahi|Ahi|Alo], B'=[Bhi|Blo|Bhi]  (fp32 accum, rel err ~5e-6)

#define DM_D   512
#define DM_KP  1536
#define DM_N1  8192
#define DM_N2  8192
#define DM_BM  128
#define DM_BN  256
#define DM_BK  64                 // bf16 elems per k-tile (128 B rows)
#define DM_KT  (DM_KP / DM_BK)    // 24
#define STAGES 3

__device__ __nv_bfloat16 g_A2[(size_t)DM_N1 * DM_KP];
__device__ __nv_bfloat16 g_B2[(size_t)DM_N2 * DM_KP];

// ---------------- PTX helpers ----------------
__device__ __forceinline__ uint32_t smem_u32(const void* p) {
    uint32_t a;
    asm("{ .reg .u64 t; cvta.to.shared.u64 t, %1; cvt.u32.u64 %0, t; }"
        : "=r"(a) : "l"(p));
    return a;
}

#define CP_ASYNC16(saddr, gptr) \
    asm volatile("cp.async.cg.shared.global [%0], [%1], 16;" :: "r"(saddr), "l"(gptr))
#define CP_COMMIT() asm volatile("cp.async.commit_group;" ::: "memory")
#define CP_WAIT(n)  asm volatile("cp.async.wait_group %0;" :: "n"(n) : "memory")

__device__ __forceinline__ void ldmx4(uint32_t* r, uint32_t addr) {
    asm volatile("ldmatrix.sync.aligned.m8n8.x4.shared.b16 {%0,%1,%2,%3}, [%4];"
                 : "=r"(r[0]), "=r"(r[1]), "=r"(r[2]), "=r"(r[3]) : "r"(addr));
}

__device__ __forceinline__ void mma16816(float* d, const uint32_t* a,
                                         uint32_t b0, uint32_t b1) {
    asm volatile(
        "mma.sync.aligned.m16n8k16.row.col.f32.bf16.bf16.f32 "
        "{%0,%1,%2,%3}, {%4,%5,%6,%7}, {%8,%9}, {%0,%1,%2,%3};"
        : "+f"(d[0]), "+f"(d[1]), "+f"(d[2]), "+f"(d[3])
        : "r"(a[0]), "r"(a[1]), "r"(a[2]), "r"(a[3]), "r"(b0), "r"(b1));
}

// ---------------- Pass 1: split conversion ----------------
__global__ __launch_bounds__(256)
void dm_convert_kernel(const float* __restrict__ A, const float* __restrict__ B,
                       const float* __restrict__ W, const int* __restrict__ tip) {
    const int idx = blockIdx.x * 256 + threadIdx.x;
    const int r  = idx >> 7;
    const int c4 = (idx & 127) * 4;
    const int ti = tip[0];

    const float4 w = *(const float4*)(W + (size_t)ti * DM_D + c4);
    const float4 a = *(const float4*)(A + (size_t)r * DM_D + c4);
    const float4 b = *(const float4*)(B + (size_t)r * DM_D + c4);

    float as[4] = {a.x * w.x, a.y * w.y, a.z * w.z, a.w * w.w};
    float bs[4] = {b.x, b.y, b.z, b.w};

    __nv_bfloat16 ah[4], al[4], bh[4], bl[4];
    #pragma unroll
    for (int i = 0; i < 4; i++) {
        ah[i] = __float2bfloat16_rn(as[i]);
        al[i] = __float2bfloat16_rn(as[i] - __bfloat162float(ah[i]));
        bh[i] = __float2bfloat16_rn(bs[i]);
        bl[i] = __float2bfloat16_rn(bs[i] - __bfloat162float(bh[i]));
    }

    __nv_bfloat16* arow = g_A2 + (size_t)r * DM_KP;
    __nv_bfloat16* brow = g_B2 + (size_t)r * DM_KP;
    *(uint2*)(arow + c4)        = *(uint2*)ah;
    *(uint2*)(arow + 512 + c4)  = *(uint2*)ah;
    *(uint2*)(arow + 1024 + c4) = *(uint2*)al;
    *(uint2*)(brow + c4)        = *(uint2*)bh;
    *(uint2*)(brow + 512 + c4)  = *(uint2*)bl;
    *(uint2*)(brow + 1024 + c4) = *(uint2*)bh;
}

// ---------------- Pass 2: GEMM ----------------
// smem: sA[STAGES][128 rows][128 B], sB[STAGES][256 rows][128 B]
// SW128 swizzle: 16B chunk c at row r -> chunk (c ^ (r & 7))
#define STG_A 16384
#define STG_B 32768
#define SMEM_TOTAL (STAGES * (STG_A + STG_B))   // 147456

__global__ __launch_bounds__(256, 1)
void dm_gemm_kernel(const float* __restrict__ bias, float* __restrict__ C) {
    extern __shared__ char smem[];
    const uint32_t sAb = smem_u32(smem);
    const uint32_t sBb = sAb + STAGES * STG_A;

    const int tid  = threadIdx.x;
    const int wid  = tid >> 5;
    const int lane = tid & 31;
    const int warp_m = wid & 1;       // 2 warps over M (64 rows each)
    const int warp_n = wid >> 1;      // 4 warps over N (64 cols each)

    const int row0 = blockIdx.y * DM_BM;
    const int col0 = blockIdx.x * DM_BN;

    // ldmatrix address precompute
    const int tile  = lane >> 3;
    const int lrow8 = lane & 7;
    const int a_trow = (tile & 1) * 8;
    const int a_tcol = tile >> 1;          // 0/1 : 16B halves of a 32B k-slice
    uint32_t aByte[4]; int aMask[4];
    #pragma unroll
    for (int mi = 0; mi < 4; mi++) {
        int r = warp_m * 64 + mi * 16 + a_trow + lrow8;
        aByte[mi] = r * 128;
        aMask[mi] = r & 7;
    }
    const int b_trow = (tile >> 1) * 8;
    const int b_tcol = tile & 1;
    uint32_t bByte[4]; int bMask[4];
    #pragma unroll
    for (int ni = 0; ni < 4; ni++) {
        int r = warp_n * 64 + ni * 16 + b_trow + lrow8;
        bByte[ni] = r * 128;
        bMask[ni] = r & 7;
    }

    float acc[4][8][4];
    #pragma unroll
    for (int mi = 0; mi < 4; mi++)
        #pragma unroll
        for (int nf = 0; nf < 8; nf++)
            #pragma unroll
            for (int q = 0; q < 4; q++) acc[mi][nf][q] = 0.0f;

    // tile loader: A 1024 chunks (4/thread), B 2048 chunks (8/thread)
    auto load_tile = [&](int kt, int s) {
        const int kb = kt * DM_BK;
        #pragma unroll
        for (int i = 0; i < 4; i++) {
            int idx = tid + i * 256;
            int r = idx >> 3, c = idx & 7;
            const __nv_bfloat16* g = g_A2 + (size_t)(row0 + r) * DM_KP + kb + c * 8;
            uint32_t sa = sAb + s * STG_A + r * 128 + ((c ^ (r & 7)) << 4);
            CP_ASYNC16(sa, g);
        }
        #pragma unroll
        for (int i = 0; i < 8; i++) {
            int idx = tid + i * 256;
            int r = idx >> 3, c = idx & 7;
            const __nv_bfloat16* g = g_B2 + (size_t)(col0 + r) * DM_KP + kb + c * 8;
            uint32_t sb = sBb + s * STG_B + r * 128 + ((c ^ (r & 7)) << 4);
            CP_ASYNC16(sb, g);
        }
    };

    // prologue
    #pragma unroll
    for (int s = 0; s < STAGES - 1; s++) {
        load_tile(s, s);
        CP_COMMIT();
    }

    // mainloop: one barrier per k-tile (24 total), rolling ks prefetch
    for (int kt = 0; kt < DM_KT; kt++) {
        CP_WAIT(STAGES - 2);
        __syncthreads();

        if (kt + STAGES - 1 < DM_KT) {
            load_tile(kt + STAGES - 1, (kt + STAGES - 1) % STAGES);
            CP_COMMIT();
        }

        const int s = kt % STAGES;
        const uint32_t sa0 = sAb + s * STG_A;
        const uint32_t sb0 = sBb + s * STG_B;

        uint32_t afr[2][4][4], bfr[2][4][4];
        // prefetch ks=0 fragments
        #pragma unroll
        for (int mi = 0; mi < 4; mi++)
            ldmx4(afr[0][mi], sa0 + aByte[mi] + ((a_tcol ^ aMask[mi]) << 4));
        #pragma unroll
        for (int ni = 0; ni < 4; ni++)
            ldmx4(bfr[0][ni], sb0 + bByte[ni] + ((b_tcol ^ bMask[ni]) << 4));

        #pragma unroll
        for (int ks = 0; ks < 4; ks++) {
            const int cur = ks & 1;
            if (ks < 3) {
                const int nxt = cur ^ 1;
                const int kc = (ks + 1) * 2;
                #pragma unroll
                for (int mi = 0; mi < 4; mi++)
                    ldmx4(afr[nxt][mi], sa0 + aByte[mi] +
                                        (((kc + a_tcol) ^ aMask[mi]) << 4));
                #pragma unroll
                for (int ni = 0; ni < 4; ni++)
                    ldmx4(bfr[nxt][ni], sb0 + bByte[ni] +
                                        (((kc + b_tcol) ^ bMask[ni]) << 4));
            }
            #pragma unroll
            for (int mi = 0; mi < 4; mi++)
                #pragma unroll
                for (int ni = 0; ni < 4; ni++) {
                    mma16816(acc[mi][ni * 2 + 0], afr[cur][mi],
                             bfr[cur][ni][0], bfr[cur][ni][1]);
                    mma16816(acc[mi][ni * 2 + 1], afr[cur][mi],
                             bfr[cur][ni][2], bfr[cur][ni][3]);
                }
        }
        // no bottom barrier: next iteration's top barrier protects stage reuse
    }

    // epilogue
    const float bv = bias[0];
    const int er = lane >> 2;
    const int ec = (lane & 3) * 2;
    #pragma unroll
    for (int mi = 0; mi < 4; mi++) {
        const int rgl = row0 + warp_m * 64 + mi * 16 + er;
        float* c0 = C + (size_t)rgl * DM_N2 + col0 + warp_n * 64 + ec;
        float* c1 = C + (size_t)(rgl + 8) * DM_N2 + col0 + warp_n * 64 + ec;
        #pragma unroll
        for (int nf = 0; nf < 8; nf++) {
            float2 v0 = {acc[mi][nf][0] + bv, acc[mi][nf][1] + bv};
            float2 v1 = {acc[mi][nf][2] + bv, acc[mi][nf][3] + bv};
            *(float2*)(c0 + nf * 8) = v0;
            *(float2*)(c1 + nf * 8) = v1;
        }
    }
}

// ---------------- launch ----------------
extern "C" void kernel_launch(void* const* d_in, const int* in_sizes, int n_in,
                              void* d_out, int out_size) {
    const float* input1     = (const float*)d_in[0];
    const float* input2     = (const float*)d_in[1];
    const float* weight     = (const float*)d_in[2];
    const float* bias       = (const float*)d_in[3];
    const int*   type_index = (const int*)  d_in[4];
    float*       out        = (float*)d_out;

    cudaFuncSetAttribute(dm_gemm_kernel,
                         cudaFuncAttributeMaxDynamicSharedMemorySize, SMEM_TOTAL);

    dm_convert_kernel<<<DM_N1 * DM_D / 4 / 256, 256>>>(
        input1, input2, weight, type_index);

    dim3 grid(DM_N2 / DM_BN, DM_N1 / DM_BM);
    dm_gemm_kernel<<<grid, 256, SMEM_TOTAL>>>(bias, out);
}

// round 11
// speedup vs baseline: 1.3511x; 1.0725x over previous
#include <cuda_runtime.h>
#include <cuda_bf16.h>
#include <cstdint>

// DistMult: C[i,j] = sum_k (A[i,k]*w_r[k]) * B[j,k] + bias
// R11 (= R9 re-bench; R10 was an infra failure, design unmeasured):
// STAGES=4 + CP_WAIT(1) => tiles kt and kt+1 both resident, so ks=3 of tile
// kt prefetches ks=0 fragments of tile kt+1. Only tile 0's first LDSM round
// is exposed. K'=1536: A'=[Ahi|Ahi|Alo], B'=[Bhi|Blo|Bhi] (fp32 accum).

#define DM_D   512
#define DM_KP  1536
#define DM_N1  8192
#define DM_N2  8192
#define DM_BM  128
#define DM_BN  256
#define DM_BK  64                 // bf16 elems per k-tile (128 B rows)
#define DM_KT  (DM_KP / DM_BK)    // 24
#define STAGES 4

__device__ __nv_bfloat16 g_A2[(size_t)DM_N1 * DM_KP];
__device__ __nv_bfloat16 g_B2[(size_t)DM_N2 * DM_KP];

// ---------------- PTX helpers ----------------
__device__ __forceinline__ uint32_t smem_u32(const void* p) {
    uint32_t a;
    asm("{ .reg .u64 t; cvta.to.shared.u64 t, %1; cvt.u32.u64 %0, t; }"
        : "=r"(a) : "l"(p));
    return a;
}

#define CP_ASYNC16(saddr, gptr) \
    asm volatile("cp.async.cg.shared.global [%0], [%1], 16;" :: "r"(saddr), "l"(gptr))
#define CP_COMMIT() asm volatile("cp.async.commit_group;" ::: "memory")
#define CP_WAIT(n)  asm volatile("cp.async.wait_group %0;" :: "n"(n) : "memory")

__device__ __forceinline__ void ldmx4(uint32_t* r, uint32_t addr) {
    asm volatile("ldmatrix.sync.aligned.m8n8.x4.shared.b16 {%0,%1,%2,%3}, [%4];"
                 : "=r"(r[0]), "=r"(r[1]), "=r"(r[2]), "=r"(r[3]) : "r"(addr));
}

__device__ __forceinline__ void mma16816(float* d, const uint32_t* a,
                                         uint32_t b0, uint32_t b1) {
    asm volatile(
        "mma.sync.aligned.m16n8k16.row.col.f32.bf16.bf16.f32 "
        "{%0,%1,%2,%3}, {%4,%5,%6,%7}, {%8,%9}, {%0,%1,%2,%3};"
        : "+f"(d[0]), "+f"(d[1]), "+f"(d[2]), "+f"(d[3])
        : "r"(a[0]), "r"(a[1]), "r"(a[2]), "r"(a[3]), "r"(b0), "r"(b1));
}

// ---------------- Pass 1: split conversion ----------------
__global__ __launch_bounds__(256)
void dm_convert_kernel(const float* __restrict__ A, const float* __restrict__ B,
                       const float* __restrict__ W, const int* __restrict__ tip) {
    const int idx = blockIdx.x * 256 + threadIdx.x;
    const int r  = idx >> 7;
    const int c4 = (idx & 127) * 4;
    const int ti = tip[0];

    const float4 w = *(const float4*)(W + (size_t)ti * DM_D + c4);
    const float4 a = *(const float4*)(A + (size_t)r * DM_D + c4);
    const float4 b = *(const float4*)(B + (size_t)r * DM_D + c4);

    float as[4] = {a.x * w.x, a.y * w.y, a.z * w.z, a.w * w.w};
    float bs[4] = {b.x, b.y, b.z, b.w};

    __nv_bfloat16 ah[4], al[4], bh[4], bl[4];
    #pragma unroll
    for (int i = 0; i < 4; i++) {
        ah[i] = __float2bfloat16_rn(as[i]);
        al[i] = __float2bfloat16_rn(as[i] - __bfloat162float(ah[i]));
        bh[i] = __float2bfloat16_rn(bs[i]);
        bl[i] = __float2bfloat16_rn(bs[i] - __bfloat162float(bh[i]));
    }

    __nv_bfloat16* arow = g_A2 + (size_t)r * DM_KP;
    __nv_bfloat16* brow = g_B2 + (size_t)r * DM_KP;
    *(uint2*)(arow + c4)        = *(uint2*)ah;
    *(uint2*)(arow + 512 + c4)  = *(uint2*)ah;
    *(uint2*)(arow + 1024 + c4) = *(uint2*)al;
    *(uint2*)(brow + c4)        = *(uint2*)bh;
    *(uint2*)(brow + 512 + c4)  = *(uint2*)bl;
    *(uint2*)(brow + 1024 + c4) = *(uint2*)bh;
}

// ---------------- Pass 2: GEMM ----------------
// smem: sA[STAGES][128 rows][128 B], sB[STAGES][256 rows][128 B]
// SW128 swizzle: 16B chunk c at row r -> chunk (c ^ (r & 7))
#define STG_A 16384
#define STG_B 32768
#define SMEM_TOTAL (STAGES * (STG_A + STG_B))   // 196608

__global__ __launch_bounds__(256, 1)
void dm_gemm_kernel(const float* __restrict__ bias, float* __restrict__ C) {
    extern __shared__ char smem[];
    const uint32_t sAb = smem_u32(smem);
    const uint32_t sBb = sAb + STAGES * STG_A;

    const int tid  = threadIdx.x;
    const int wid  = tid >> 5;
    const int lane = tid & 31;
    const int warp_m = wid & 1;       // 2 warps over M (64 rows each)
    const int warp_n = wid >> 1;      // 4 warps over N (64 cols each)

    const int row0 = blockIdx.y * DM_BM;
    const int col0 = blockIdx.x * DM_BN;

    // ldmatrix address precompute
    const int tile  = lane >> 3;
    const int lrow8 = lane & 7;
    const int a_trow = (tile & 1) * 8;
    const int a_tcol = tile >> 1;
    uint32_t aByte[4]; int aMask[4];
    #pragma unroll
    for (int mi = 0; mi < 4; mi++) {
        int r = warp_m * 64 + mi * 16 + a_trow + lrow8;
        aByte[mi] = r * 128;
        aMask[mi] = r & 7;
    }
    const int b_trow = (tile >> 1) * 8;
    const int b_tcol = tile & 1;
    uint32_t bByte[4]; int bMask[4];
    #pragma unroll
    for (int ni = 0; ni < 4; ni++) {
        int r = warp_n * 64 + ni * 16 + b_trow + lrow8;
        bByte[ni] = r * 128;
        bMask[ni] = r & 7;
    }

    float acc[4][8][4];
    #pragma unroll
    for (int mi = 0; mi < 4; mi++)
        #pragma unroll
        for (int nf = 0; nf < 8; nf++)
            #pragma unroll
            for (int q = 0; q < 4; q++) acc[mi][nf][q] = 0.0f;

    // tile loader: A 1024 chunks (4/thread), B 2048 chunks (8/thread)
    auto load_tile = [&](int kt, int s) {
        const int kb = kt * DM_BK;
        #pragma unroll
        for (int i = 0; i < 4; i++) {
            int idx = tid + i * 256;
            int r = idx >> 3, c = idx & 7;
            const __nv_bfloat16* g = g_A2 + (size_t)(row0 + r) * DM_KP + kb + c * 8;
            uint32_t sa = sAb + s * STG_A + r * 128 + ((c ^ (r & 7)) << 4);
            CP_ASYNC16(sa, g);
        }
        #pragma unroll
        for (int i = 0; i < 8; i++) {
            int idx = tid + i * 256;
            int r = idx >> 3, c = idx & 7;
            const __nv_bfloat16* g = g_B2 + (size_t)(col0 + r) * DM_KP + kb + c * 8;
            uint32_t sb = sBb + s * STG_B + r * 128 + ((c ^ (r & 7)) << 4);
            CP_ASYNC16(sb, g);
        }
    };

    uint32_t afr[2][4][4], bfr[2][4][4];

    // fragment loader: buffer buf <- k-slice kc (0,2,4,6) of stage (sa0,sb0)
    auto frag_load = [&](int buf, uint32_t sa0, uint32_t sb0, int kc) {
        #pragma unroll
        for (int mi = 0; mi < 4; mi++)
            ldmx4(afr[buf][mi], sa0 + aByte[mi] +
                                (((kc + a_tcol) ^ aMask[mi]) << 4));
        #pragma unroll
        for (int ni = 0; ni < 4; ni++)
            ldmx4(bfr[buf][ni], sb0 + bByte[ni] +
                                (((kc + b_tcol) ^ bMask[ni]) << 4));
    };

    // prologue: fill STAGES-1 = 3 stages
    #pragma unroll
    for (int s = 0; s < STAGES - 1; s++) {
        load_tile(s, s);
        CP_COMMIT();
    }

    // tile 0: wait until stages 0 and 1 are resident, load first fragments
    CP_WAIT(1);
    __syncthreads();
    frag_load(0, sAb, sBb, 0);    // the only exposed LDSM round

    // mainloop
    for (int kt = 0; kt < DM_KT; kt++) {
        if (kt > 0) {
            // tiles kt AND kt+1 guaranteed resident after this wait+barrier
            CP_WAIT(1);
            __syncthreads();
        }

        if (kt + STAGES - 1 < DM_KT) {
            load_tile(kt + STAGES - 1, (kt + STAGES - 1) % STAGES);
            CP_COMMIT();
        }

        const int s = kt % STAGES;
        const uint32_t sa0 = sAb + s * STG_A;
        const uint32_t sb0 = sBb + s * STG_B;

        #pragma unroll
        for (int ks = 0; ks < 4; ks++) {
            const int cur = ks & 1;
            const int nxt = cur ^ 1;
            if (ks < 3) {
                frag_load(nxt, sa0, sb0, (ks + 1) * 2);
            } else {
                // prefetch ks=0 of NEXT tile (stage (kt+1)%STAGES is resident
                // and not overwritten this iter, which writes (kt+3)%STAGES)
                const int ktn = (kt + 1 < DM_KT) ? kt + 1 : kt;
                const int sn = ktn % STAGES;
                frag_load(nxt, sAb + sn * STG_A, sBb + sn * STG_B, 0);
            }
            #pragma unroll
            for (int mi = 0; mi < 4; mi++)
                #pragma unroll
                for (int ni = 0; ni < 4; ni++) {
                    mma16816(acc[mi][ni * 2 + 0], afr[cur][mi],
                             bfr[cur][ni][0], bfr[cur][ni][1]);
                    mma16816(acc[mi][ni * 2 + 1], afr[cur][mi],
                             bfr[cur][ni][2], bfr[cur][ni][3]);
                }
        }
    }

    // epilogue
    const float bv = bias[0];
    const int er = lane >> 2;
    const int ec = (lane & 3) * 2;
    #pragma unroll
    for (int mi = 0; mi < 4; mi++) {
        const int rgl = row0 + warp_m * 64 + mi * 16 + er;
        float* c0 = C + (size_t)rgl * DM_N2 + col0 + warp_n * 64 + ec;
        float* c1 = C + (size_t)(rgl + 8) * DM_N2 + col0 + warp_n * 64 + ec;
        #pragma unroll
        for (int nf = 0; nf < 8; nf++) {
            float2 v0 = {acc[mi][nf][0] + bv, acc[mi][nf][1] + bv};
            float2 v1 = {acc[mi][nf][2] + bv, acc[mi][nf][3] + bv};
            *(float2*)(c0 + nf * 8) = v0;
            *(float2*)(c1 + nf * 8) = v1;
        }
    }
}

// ---------------- launch ----------------
extern "C" void kernel_launch(void* const* d_in, const int* in_sizes, int n_in,
                              void* d_out, int out_size) {
    const float* input1     = (const float*)d_in[0];
    const float* input2     = (const float*)d_in[1];
    const float* weight     = (const float*)d_in[2];
    const float* bias       = (const float*)d_in[3];
    const int*   type_index = (const int*)  d_in[4];
    float*       out        = (float*)d_out;

    cudaFuncSetAttribute(dm_gemm_kernel,
                         cudaFuncAttributeMaxDynamicSharedMemorySize, SMEM_TOTAL);

    dm_convert_kernel<<<DM_N1 * DM_D / 4 / 256, 256>>>(
        input1, input2, weight, type_index);

    dim3 grid(DM_N2 / DM_BN, DM_N1 / DM_BM);
    dm_gemm_kernel<<<grid, 256, SMEM_TOTAL>>>(bias, out);
}

// round 12
// speedup vs baseline: 1.4474x; 1.0713x over previous
#include <cuda_runtime.h>
#include <cuda_bf16.h>
#include <cstdint>

// DistMult: C[i,j] = sum_k (A[i,k]*w_r[k]) * B[j,k] + bias
// R12: drop the K'=1536 duplication. Physical K=512, 8 tiles of 64.
// Per stage: {Ahi, Alo, Bhi, Blo} planes (96 KB), STAGES=2.
// Per 16-k-slice: 16 ldmx4 -> 96 MMAs (P1=Ahi*Bhi, P2=Ahi*Blo, P3=Alo*Bhi),
// fragments shared across products => 33% less LDSM + L2 traffic, 8 barriers.
// fp32 accum; dropped Alo*Blo term => rel err ~5e-6.

#define DM_D   512
#define DM_N1  8192
#define DM_N2  8192
#define DM_BM  128
#define DM_BN  256
#define DM_BK  64                 // physical k per tile (128 B rows)
#define DM_KT  (DM_D / DM_BK)     // 8
#define STAGES 2

// Split planes, row-major [N][1024]: [0,512)=hi, [512,1024)=lo.
__device__ __nv_bfloat16 g_A2[(size_t)DM_N1 * 1024];
__device__ __nv_bfloat16 g_B2[(size_t)DM_N2 * 1024];

// ---------------- PTX helpers ----------------
__device__ __forceinline__ uint32_t smem_u32(const void* p) {
    uint32_t a;
    asm("{ .reg .u64 t; cvta.to.shared.u64 t, %1; cvt.u32.u64 %0, t; }"
        : "=r"(a) : "l"(p));
    return a;
}

#define CP_ASYNC16(saddr, gptr) \
    asm volatile("cp.async.cg.shared.global [%0], [%1], 16;" :: "r"(saddr), "l"(gptr))
#define CP_COMMIT() asm volatile("cp.async.commit_group;" ::: "memory")
#define CP_WAIT(n)  asm volatile("cp.async.wait_group %0;" :: "n"(n) : "memory")

__device__ __forceinline__ void ldmx4(uint32_t* r, uint32_t addr) {
    asm volatile("ldmatrix.sync.aligned.m8n8.x4.shared.b16 {%0,%1,%2,%3}, [%4];"
                 : "=r"(r[0]), "=r"(r[1]), "=r"(r[2]), "=r"(r[3]) : "r"(addr));
}

__device__ __forceinline__ void mma16816(float* d, const uint32_t* a,
                                         uint32_t b0, uint32_t b1) {
    asm volatile(
        "mma.sync.aligned.m16n8k16.row.col.f32.bf16.bf16.f32 "
        "{%0,%1,%2,%3}, {%4,%5,%6,%7}, {%8,%9}, {%0,%1,%2,%3};"
        : "+f"(d[0]), "+f"(d[1]), "+f"(d[2]), "+f"(d[3])
        : "r"(a[0]), "r"(a[1]), "r"(a[2]), "r"(a[3]), "r"(b0), "r"(b1));
}

// ---------------- Pass 1: split conversion ----------------
__global__ __launch_bounds__(256)
void dm_convert_kernel(const float* __restrict__ A, const float* __restrict__ B,
                       const float* __restrict__ W, const int* __restrict__ tip) {
    const int idx = blockIdx.x * 256 + threadIdx.x;
    const int r  = idx >> 7;
    const int c4 = (idx & 127) * 4;
    const int ti = tip[0];

    const float4 w = *(const float4*)(W + (size_t)ti * DM_D + c4);
    const float4 a = *(const float4*)(A + (size_t)r * DM_D + c4);
    const float4 b = *(const float4*)(B + (size_t)r * DM_D + c4);

    float as[4] = {a.x * w.x, a.y * w.y, a.z * w.z, a.w * w.w};
    float bs[4] = {b.x, b.y, b.z, b.w};

    __nv_bfloat16 ah[4], al[4], bh[4], bl[4];
    #pragma unroll
    for (int i = 0; i < 4; i++) {
        ah[i] = __float2bfloat16_rn(as[i]);
        al[i] = __float2bfloat16_rn(as[i] - __bfloat162float(ah[i]));
        bh[i] = __float2bfloat16_rn(bs[i]);
        bl[i] = __float2bfloat16_rn(bs[i] - __bfloat162float(bh[i]));
    }

    __nv_bfloat16* arow = g_A2 + (size_t)r * 1024;
    __nv_bfloat16* brow = g_B2 + (size_t)r * 1024;
    *(uint2*)(arow + c4)       = *(uint2*)ah;
    *(uint2*)(arow + 512 + c4) = *(uint2*)al;
    *(uint2*)(brow + c4)       = *(uint2*)bh;
    *(uint2*)(brow + 512 + c4) = *(uint2*)bl;
}

// ---------------- Pass 2: GEMM ----------------
// stage = { Ahi 16K | Alo 16K | Bhi 32K | Blo 32K } ; SW128: chunk c ^= (r&7)
#define OFF_AHI 0
#define OFF_ALO 16384
#define OFF_BHI 32768
#define OFF_BLO 65536
#define STG_BYTES 98304
#define SMEM_TOTAL (STAGES * STG_BYTES)   // 196608

__global__ __launch_bounds__(256, 1)
void dm_gemm_kernel(const float* __restrict__ bias, float* __restrict__ C) {
    extern __shared__ char smem[];
    const uint32_t sbase = smem_u32(smem);

    const int tid  = threadIdx.x;
    const int wid  = tid >> 5;
    const int lane = tid & 31;
    const int warp_m = wid & 1;       // 2 warps over M (64 rows each)
    const int warp_n = wid >> 1;      // 4 warps over N (64 cols each)

    const int row0 = blockIdx.y * DM_BM;
    const int col0 = blockIdx.x * DM_BN;

    // ldmatrix address precompute (128 B rows, SW128)
    const int tile  = lane >> 3;
    const int lrow8 = lane & 7;
    const int a_trow = (tile & 1) * 8;
    const int a_tcol = tile >> 1;
    uint32_t aByte[4]; int aMask[4];
    #pragma unroll
    for (int mi = 0; mi < 4; mi++) {
        int r = warp_m * 64 + mi * 16 + a_trow + lrow8;
        aByte[mi] = r * 128;
        aMask[mi] = r & 7;
    }
    const int b_trow = (tile >> 1) * 8;
    const int b_tcol = tile & 1;
    uint32_t bByte[4]; int bMask[4];
    #pragma unroll
    for (int ni = 0; ni < 4; ni++) {
        int r = warp_n * 64 + ni * 16 + b_trow + lrow8;
        bByte[ni] = r * 128;
        bMask[ni] = r & 7;
    }

    float acc[4][8][4];
    #pragma unroll
    for (int mi = 0; mi < 4; mi++)
        #pragma unroll
        for (int nf = 0; nf < 8; nf++)
            #pragma unroll
            for (int q = 0; q < 4; q++) acc[mi][nf][q] = 0.0f;

    // tile loader: per plane, A=1024 16B chunks (4/thread), B=2048 (8/thread)
    auto load_tile = [&](int kt, int s) {
        const int kb = kt * DM_BK;
        const uint32_t stg = sbase + s * STG_BYTES;
        #pragma unroll
        for (int i = 0; i < 4; i++) {
            int idx = tid + i * 256;
            int r = idx >> 3, c = idx & 7;
            const size_t ga = (size_t)(row0 + r) * 1024 + kb + c * 8;
            uint32_t so = r * 128 + ((c ^ (r & 7)) << 4);
            CP_ASYNC16(stg + OFF_AHI + so, g_A2 + ga);
            CP_ASYNC16(stg + OFF_ALO + so, g_A2 + ga + 512);
        }
        #pragma unroll
        for (int i = 0; i < 8; i++) {
            int idx = tid + i * 256;
            int r = idx >> 3, c = idx & 7;
            const size_t gb = (size_t)(col0 + r) * 1024 + kb + c * 8;
            uint32_t so = r * 128 + ((c ^ (r & 7)) << 4);
            CP_ASYNC16(stg + OFF_BHI + so, g_B2 + gb);
            CP_ASYNC16(stg + OFF_BLO + so, g_B2 + gb + 512);
        }
    };

    uint32_t aHi[4][4], aLo[4][4], bLo[4][4], bHiD[2][4][4];

    auto ldA = [&](uint32_t (*dst)[4], uint32_t base, int kc) {
        #pragma unroll
        for (int mi = 0; mi < 4; mi++)
            ldmx4(dst[mi], base + aByte[mi] + (((kc + a_tcol) ^ aMask[mi]) << 4));
    };
    auto ldB = [&](uint32_t (*dst)[4], uint32_t base, int kc) {
        #pragma unroll
        for (int ni = 0; ni < 4; ni++)
            ldmx4(dst[ni], base + bByte[ni] + (((kc + b_tcol) ^ bMask[ni]) << 4));
    };
    auto mma_block = [&](uint32_t (*af)[4], uint32_t (*bf)[4]) {
        #pragma unroll
        for (int mi = 0; mi < 4; mi++)
            #pragma unroll
            for (int ni = 0; ni < 4; ni++) {
                mma16816(acc[mi][ni * 2 + 0], af[mi], bf[ni][0], bf[ni][1]);
                mma16816(acc[mi][ni * 2 + 1], af[mi], bf[ni][2], bf[ni][3]);
            }
    };

    // prologue: stage 0 = tile 0, stage 1 = tile 1
    load_tile(0, 0); CP_COMMIT();
    load_tile(1, 1); CP_COMMIT();
    CP_WAIT(1);
    __syncthreads();

    for (int kt = 0; kt < DM_KT; kt++) {
        const uint32_t stg = sbase + (kt & 1) * STG_BYTES;
        const uint32_t sAhi = stg + OFF_AHI;
        const uint32_t sAlo = stg + OFF_ALO;
        const uint32_t sBhi = stg + OFF_BHI;
        const uint32_t sBlo = stg + OFF_BLO;

        // exposed tile-start loads: Ahi, Bhi for ks=0
        ldA(aHi, sAhi, 0);
        ldB(bHiD[0], sBhi, 0);

        #pragma unroll
        for (int ks = 0; ks < 4; ks++) {
            const int p = ks & 1;
            const int kc = ks * 2;
            // prefetch Alo,Blo of this slice (hidden under P1)
            ldA(aLo, sAlo, kc);
            ldB(bLo, sBlo, kc);
            mma_block(aHi, bHiD[p]);                 // P1 = Ahi*Bhi
            if (ks < 3) ldB(bHiD[p ^ 1], sBhi, kc + 2);  // Bhi(ks+1)
            mma_block(aHi, bLo);                     // P2 = Ahi*Blo
            if (ks < 3) ldA(aHi, sAhi, kc + 2);      // Ahi(ks+1)
            mma_block(aLo, bHiD[p]);                 // P3 = Alo*Bhi
        }

        if (kt < DM_KT - 1) {
            CP_WAIT(0);            // tile kt+1 fully resident (this thread)
            __syncthreads();       // CTA-wide visibility + stage kt reusable
            if (kt + 2 < DM_KT) {
                load_tile(kt + 2, kt & 1);
                CP_COMMIT();
            }
        }
    }

    // epilogue
    const float bv = bias[0];
    const int er = lane >> 2;
    const int ec = (lane & 3) * 2;
    #pragma unroll
    for (int mi = 0; mi < 4; mi++) {
        const int rgl = row0 + warp_m * 64 + mi * 16 + er;
        float* c0 = C + (size_t)rgl * DM_N2 + col0 + warp_n * 64 + ec;
        float* c1 = C + (size_t)(rgl + 8) * DM_N2 + col0 + warp_n * 64 + ec;
        #pragma unroll
        for (int nf = 0; nf < 8; nf++) {
            float2 v0 = {acc[mi][nf][0] + bv, acc[mi][nf][1] + bv};
            float2 v1 = {acc[mi][nf][2] + bv, acc[mi][nf][3] + bv};
            *(float2*)(c0 + nf * 8) = v0;
            *(float2*)(c1 + nf * 8) = v1;
        }
    }
}

// ---------------- launch ----------------
extern "C" void kernel_launch(void* const* d_in, const int* in_sizes, int n_in,
                              void* d_out, int out_size) {
    const float* input1     = (const float*)d_in[0];
    const float* input2     = (const float*)d_in[1];
    const float* weight     = (const float*)d_in[2];
    const float* bias       = (const float*)d_in[3];
    const int*   type_index = (const int*)  d_in[4];
    float*       out        = (float*)d_out;

    cudaFuncSetAttribute(dm_gemm_kernel,
                         cudaFuncAttributeMaxDynamicSharedMemorySize, SMEM_TOTAL);

    dm_convert_kernel<<<DM_N1 * DM_D / 4 / 256, 256>>>(
        input1, input2, weight, type_index);

    dim3 grid(DM_N2 / DM_BN, DM_N1 / DM_BM);
    dm_gemm_kernel<<<grid, 256, SMEM_TOTAL>>>(bias, out);
}

// round 14
// speedup vs baseline: 1.4854x; 1.0263x over previous
#include <cuda_runtime.h>
#include <cuda_bf16.h>
#include <cstdint>

// DistMult: C[i,j] = sum_k (A[i,k]*w_r[k]) * B[j,k] + bias
// R14 (= R13 re-bench; R13 bench was an infra failure, design unmeasured):
// R12 + hoisted CP_WAIT/barrier into ks=3 (overlaps draining MMA queue)
// + cross-tile fragment prefetch (ks=3 prefetches next tile's ks=0 frags)
// + earlier load_tile(kt+2) issue. Only tile 0's first LDSM round exposed.
// 3 products P1=Ahi*Bhi, P2=Ahi*Blo, P3=Alo*Bhi; fp32 accum; rel err ~5e-6.

#define DM_D   512
#define DM_N1  8192
#define DM_N2  8192
#define DM_BM  128
#define DM_BN  256
#define DM_BK  64                 // physical k per tile (128 B rows)
#define DM_KT  (DM_D / DM_BK)     // 8
#define STAGES 2

// Split planes, row-major [N][1024]: [0,512)=hi, [512,1024)=lo.
__device__ __nv_bfloat16 g_A2[(size_t)DM_N1 * 1024];
__device__ __nv_bfloat16 g_B2[(size_t)DM_N2 * 1024];

// ---------------- PTX helpers ----------------
__device__ __forceinline__ uint32_t smem_u32(const void* p) {
    uint32_t a;
    asm("{ .reg .u64 t; cvta.to.shared.u64 t, %1; cvt.u32.u64 %0, t; }"
        : "=r"(a) : "l"(p));
    return a;
}

#define CP_ASYNC16(saddr, gptr) \
    asm volatile("cp.async.cg.shared.global [%0], [%1], 16;" :: "r"(saddr), "l"(gptr))
#define CP_COMMIT() asm volatile("cp.async.commit_group;" ::: "memory")
#define CP_WAIT(n)  asm volatile("cp.async.wait_group %0;" :: "n"(n) : "memory")

__device__ __forceinline__ void ldmx4(uint32_t* r, uint32_t addr) {
    asm volatile("ldmatrix.sync.aligned.m8n8.x4.shared.b16 {%0,%1,%2,%3}, [%4];"
                 : "=r"(r[0]), "=r"(r[1]), "=r"(r[2]), "=r"(r[3]) : "r"(addr));
}

__device__ __forceinline__ void mma16816(float* d, const uint32_t* a,
                                         uint32_t b0, uint32_t b1) {
    asm volatile(
        "mma.sync.aligned.m16n8k16.row.col.f32.bf16.bf16.f32 "
        "{%0,%1,%2,%3}, {%4,%5,%6,%7}, {%8,%9}, {%0,%1,%2,%3};"
        : "+f"(d[0]), "+f"(d[1]), "+f"(d[2]), "+f"(d[3])
        : "r"(a[0]), "r"(a[1]), "r"(a[2]), "r"(a[3]), "r"(b0), "r"(b1));
}

// ---------------- Pass 1: split conversion ----------------
__global__ __launch_bounds__(256)
void dm_convert_kernel(const float* __restrict__ A, const float* __restrict__ B,
                       const float* __restrict__ W, const int* __restrict__ tip) {
    const int idx = blockIdx.x * 256 + threadIdx.x;
    const int r  = idx >> 7;
    const int c4 = (idx & 127) * 4;
    const int ti = tip[0];

    const float4 w = *(const float4*)(W + (size_t)ti * DM_D + c4);
    const float4 a = *(const float4*)(A + (size_t)r * DM_D + c4);
    const float4 b = *(const float4*)(B + (size_t)r * DM_D + c4);

    float as[4] = {a.x * w.x, a.y * w.y, a.z * w.z, a.w * w.w};
    float bs[4] = {b.x, b.y, b.z, b.w};

    __nv_bfloat16 ah[4], al[4], bh[4], bl[4];
    #pragma unroll
    for (int i = 0; i < 4; i++) {
        ah[i] = __float2bfloat16_rn(as[i]);
        al[i] = __float2bfloat16_rn(as[i] - __bfloat162float(ah[i]));
        bh[i] = __float2bfloat16_rn(bs[i]);
        bl[i] = __float2bfloat16_rn(bs[i] - __bfloat162float(bh[i]));
    }

    __nv_bfloat16* arow = g_A2 + (size_t)r * 1024;
    __nv_bfloat16* brow = g_B2 + (size_t)r * 1024;
    *(uint2*)(arow + c4)       = *(uint2*)ah;
    *(uint2*)(arow + 512 + c4) = *(uint2*)al;
    *(uint2*)(brow + c4)       = *(uint2*)bh;
    *(uint2*)(brow + 512 + c4) = *(uint2*)bl;
}

// ---------------- Pass 2: GEMM ----------------
// stage = { Ahi 16K | Alo 16K | Bhi 32K | Blo 32K } ; SW128: chunk c ^= (r&7)
#define OFF_AHI 0
#define OFF_ALO 16384
#define OFF_BHI 32768
#define OFF_BLO 65536
#define STG_BYTES 98304
#define SMEM_TOTAL (STAGES * STG_BYTES)   // 196608

__global__ __launch_bounds__(256, 1)
void dm_gemm_kernel(const float* __restrict__ bias, float* __restrict__ C) {
    extern __shared__ char smem[];
    const uint32_t sbase = smem_u32(smem);

    const int tid  = threadIdx.x;
    const int wid  = tid >> 5;
    const int lane = tid & 31;
    const int warp_m = wid & 1;       // 2 warps over M (64 rows each)
    const int warp_n = wid >> 1;      // 4 warps over N (64 cols each)

    const int row0 = blockIdx.y * DM_BM;
    const int col0 = blockIdx.x * DM_BN;

    // ldmatrix address precompute (128 B rows, SW128)
    const int tile  = lane >> 3;
    const int lrow8 = lane & 7;
    const int a_trow = (tile & 1) * 8;
    const int a_tcol = tile >> 1;
    uint32_t aByte[4]; int aMask[4];
    #pragma unroll
    for (int mi = 0; mi < 4; mi++) {
        int r = warp_m * 64 + mi * 16 + a_trow + lrow8;
        aByte[mi] = r * 128;
        aMask[mi] = r & 7;
    }
    const int b_trow = (tile >> 1) * 8;
    const int b_tcol = tile & 1;
    uint32_t bByte[4]; int bMask[4];
    #pragma unroll
    for (int ni = 0; ni < 4; ni++) {
        int r = warp_n * 64 + ni * 16 + b_trow + lrow8;
        bByte[ni] = r * 128;
        bMask[ni] = r & 7;
    }

    float acc[4][8][4];
    #pragma unroll
    for (int mi = 0; mi < 4; mi++)
        #pragma unroll
        for (int nf = 0; nf < 8; nf++)
            #pragma unroll
            for (int q = 0; q < 4; q++) acc[mi][nf][q] = 0.0f;

    // tile loader: per plane, A=1024 16B chunks (4/thread), B=2048 (8/thread)
    auto load_tile = [&](int kt, int s) {
        const int kb = kt * DM_BK;
        const uint32_t stg = sbase + s * STG_BYTES;
        #pragma unroll
        for (int i = 0; i < 4; i++) {
            int idx = tid + i * 256;
            int r = idx >> 3, c = idx & 7;
            const size_t ga = (size_t)(row0 + r) * 1024 + kb + c * 8;
            uint32_t so = r * 128 + ((c ^ (r & 7)) << 4);
            CP_ASYNC16(stg + OFF_AHI + so, g_A2 + ga);
            CP_ASYNC16(stg + OFF_ALO + so, g_A2 + ga + 512);
        }
        #pragma unroll
        for (int i = 0; i < 8; i++) {
            int idx = tid + i * 256;
            int r = idx >> 3, c = idx & 7;
            const size_t gb = (size_t)(col0 + r) * 1024 + kb + c * 8;
            uint32_t so = r * 128 + ((c ^ (r & 7)) << 4);
            CP_ASYNC16(stg + OFF_BHI + so, g_B2 + gb);
            CP_ASYNC16(stg + OFF_BLO + so, g_B2 + gb + 512);
        }
    };

    uint32_t aHi[4][4], aLo[4][4], bLo[4][4], bHiD[2][4][4];

    auto ldA = [&](uint32_t (*dst)[4], uint32_t base, int kc) {
        #pragma unroll
        for (int mi = 0; mi < 4; mi++)
            ldmx4(dst[mi], base + aByte[mi] + (((kc + a_tcol) ^ aMask[mi]) << 4));
    };
    auto ldB = [&](uint32_t (*dst)[4], uint32_t base, int kc) {
        #pragma unroll
        for (int ni = 0; ni < 4; ni++)
            ldmx4(dst[ni], base + bByte[ni] + (((kc + b_tcol) ^ bMask[ni]) << 4));
    };
    auto mma_block = [&](uint32_t (*af)[4], uint32_t (*bf)[4]) {
        #pragma unroll
        for (int mi = 0; mi < 4; mi++)
            #pragma unroll
            for (int ni = 0; ni < 4; ni++) {
                mma16816(acc[mi][ni * 2 + 0], af[mi], bf[ni][0], bf[ni][1]);
                mma16816(acc[mi][ni * 2 + 1], af[mi], bf[ni][2], bf[ni][3]);
            }
    };

    // prologue: stage 0 = tile 0, stage 1 = tile 1
    load_tile(0, 0); CP_COMMIT();
    load_tile(1, 1); CP_COMMIT();
    CP_WAIT(1);
    __syncthreads();

    // tile 0 start fragments — the only exposed LDSM round
    ldA(aHi, sbase + OFF_AHI, 0);
    ldB(bHiD[0], sbase + OFF_BHI, 0);

    for (int kt = 0; kt < DM_KT; kt++) {
        const uint32_t stg  = sbase + (kt & 1) * STG_BYTES;
        const uint32_t nstg = sbase + ((kt + 1) & 1) * STG_BYTES;
        const bool has_next = (kt < DM_KT - 1);

        #pragma unroll
        for (int ks = 0; ks < 4; ks++) {
            const int p = ks & 1;
            const int kc = ks * 2;

            // this slice's lo fragments (last reads of stage kt when ks==3)
            ldA(aLo, stg + OFF_ALO, kc);
            ldB(bLo, stg + OFF_BLO, kc);

            if (ks == 3 && has_next) {
                // stage kt fully read by every warp after this barrier;
                // overlaps the still-draining ks<=2 MMA queue.
                CP_WAIT(0);
                __syncthreads();
                if (kt + 2 < DM_KT) {
                    load_tile(kt + 2, kt & 1);   // overwrite stage kt
                    CP_COMMIT();
                }
            }

            mma_block(aHi, bHiD[p]);                       // P1 = Ahi*Bhi
            if (ks < 3)        ldB(bHiD[p ^ 1], stg + OFF_BHI, kc + 2);
            else if (has_next) ldB(bHiD[p ^ 1], nstg + OFF_BHI, 0);  // next tile ks=0
            mma_block(aHi, bLo);                           // P2 = Ahi*Blo
            if (ks < 3)        ldA(aHi, stg + OFF_AHI, kc + 2);
            else if (has_next) ldA(aHi, nstg + OFF_AHI, 0);          // next tile ks=0
            mma_block(aLo, bHiD[p]);                       // P3 = Alo*Bhi
        }
    }

    // epilogue
    const float bv = bias[0];
    const int er = lane >> 2;
    const int ec = (lane & 3) * 2;
    #pragma unroll
    for (int mi = 0; mi < 4; mi++) {
        const int rgl = row0 + warp_m * 64 + mi * 16 + er;
        float* c0 = C + (size_t)rgl * DM_N2 + col0 + warp_n * 64 + ec;
        float* c1 = C + (size_t)(rgl + 8) * DM_N2 + col0 + warp_n * 64 + ec;
        #pragma unroll
        for (int nf = 0; nf < 8; nf++) {
            float2 v0 = {acc[mi][nf][0] + bv, acc[mi][nf][1] + bv};
            float2 v1 = {acc[mi][nf][2] + bv, acc[mi][nf][3] + bv};
            *(float2*)(c0 + nf * 8) = v0;
            *(float2*)(c1 + nf * 8) = v1;
        }
    }
}

// ---------------- launch ----------------
extern "C" void kernel_launch(void* const* d_in, const int* in_sizes, int n_in,
                              void* d_out, int out_size) {
    const float* input1     = (const float*)d_in[0];
    const float* input2     = (const float*)d_in[1];
    const float* weight     = (const float*)d_in[2];
    const float* bias       = (const float*)d_in[3];
    const int*   type_index = (const int*)  d_in[4];
    float*       out        = (float*)d_out;

    cudaFuncSetAttribute(dm_gemm_kernel,
                         cudaFuncAttributeMaxDynamicSharedMemorySize, SMEM_TOTAL);

    dm_convert_kernel<<<DM_N1 * DM_D / 4 / 256, 256>>>(
        input1, input2, weight, type_index);

    dim3 grid(DM_N2 / DM_BN, DM_N1 / DM_BM);
    dm_gemm_kernel<<<grid, 256, SMEM_TOTAL>>>(bias, out);
}